// round 3
// baseline (speedup 1.0000x reference)
#include <cuda_runtime.h>

#define N_NODES  50000
#define N_EDGES  800000
#define HIDDEN   128
#define N_GRAPHS 256
#define N_CLASSES 10

// -------- device scratch (no allocations allowed) --------
__device__ __align__(16) float g_agg[N_NODES * HIDDEN];
__device__ __align__(16) float g_f1[N_NODES * HIDDEN];
__device__ __align__(16) float g_f2[N_NODES * HIDDEN];
__device__ int   g_deg[N_NODES];
__device__ int   g_off[N_NODES + 1];
__device__ int   g_cur[N_NODES];
__device__ int   g_csr[N_EDGES];
__device__ __align__(16) float g_pooled[N_GRAPHS * HIDDEN];

// selector: 0 -> external x, 1 -> g_f1, 2 -> g_f2
__device__ __forceinline__ const float* pick_feat(int sel, const float* x) {
    return sel == 0 ? x : (sel == 1 ? g_f1 : g_f2);
}
__device__ __forceinline__ float* pick_out(int sel) {
    return sel == 1 ? g_f1 : g_f2;
}

__device__ __forceinline__ int clamp_node(int v) {
    v = v < 0 ? 0 : v;
    return v >= N_NODES ? N_NODES - 1 : v;
}

// ---------------- CSR build ----------------
__global__ void zero_deg_k() {
    int i = blockIdx.x * blockDim.x + threadIdx.x;
    if (i < N_NODES) g_deg[i] = 0;
}

// edge_index is int32: row 0 = src (first N_EDGES), row 1 = dst (second N_EDGES)
__global__ void hist_k(const int* __restrict__ ei) {
    int e = blockIdx.x * blockDim.x + threadIdx.x;
    if (e < N_EDGES) {
        int d = clamp_node(ei[N_EDGES + e]);
        atomicAdd(&g_deg[d], 1);
    }
}

// single-block exclusive scan over 50000 ints (1024 threads, ~49 items each)
__global__ void scan_k() {
    const int T = 1024;
    const int ITEMS = (N_NODES + T - 1) / T;  // 49
    int tid = threadIdx.x;
    int base = tid * ITEMS;

    int s = 0;
    for (int i = 0; i < ITEMS; i++) {
        int idx = base + i;
        int v = (idx < N_NODES) ? g_deg[idx] : 0;
        s += v;
    }
    __shared__ int sh[T];
    sh[tid] = s;
    __syncthreads();
    // inclusive Hillis-Steele scan
    for (int d = 1; d < T; d <<= 1) {
        int t = (tid >= d) ? sh[tid - d] : 0;
        __syncthreads();
        sh[tid] += t;
        __syncthreads();
    }
    int run = sh[tid] - s;  // exclusive prefix for this thread's chunk
    for (int i = 0; i < ITEMS; i++) {
        int idx = base + i;
        if (idx < N_NODES) {
            g_off[idx] = run;
            g_cur[idx] = run;
            run += g_deg[idx];
        }
    }
    if (tid == T - 1) g_off[N_NODES] = sh[T - 1];
}

__global__ void fill_k(const int* __restrict__ ei) {
    int e = blockIdx.x * blockDim.x + threadIdx.x;
    if (e < N_EDGES) {
        int s = clamp_node(ei[e]);
        int d = clamp_node(ei[N_EDGES + e]);
        int slot = atomicAdd(&g_cur[d], 1);
        if (slot >= 0 && slot < N_EDGES) g_csr[slot] = s;
    }
}

// ---------------- edge aggregation: warp per node ----------------
__global__ void agg_k(int insel, const float* __restrict__ x) {
    int w    = (blockIdx.x * blockDim.x + threadIdx.x) >> 5;
    int lane = threadIdx.x & 31;
    if (w >= N_NODES) return;
    const float* feat = pick_feat(insel, x);
    int lo = g_off[w], hi = g_off[w + 1];
    const float4* f4 = (const float4*)feat;
    float4 acc = make_float4(0.f, 0.f, 0.f, 0.f);
    for (int j = lo; j < hi; j++) {
        int s = g_csr[j];
        float4 v = f4[s * 32 + lane];
        acc.x += v.x; acc.y += v.y; acc.z += v.z; acc.w += v.w;
    }
    ((float4*)g_agg)[w * 32 + lane] = acc;
}

// ---------------- fused 2-layer MLP ----------------
// out = relu?( relu((feat+agg)@W1 + b1) @ W2 + b2 )
// tile: 64 nodes x 128 cols per block, 256 threads, 8 rows x 4 cols per thread
// smem: INP 64x128 (32KB, reused for MID) + W k-chunk 32x128 (16KB) = 48KB static
__global__ void __launch_bounds__(256) mlp_k(
        int insel, const float* __restrict__ x,
        const float* __restrict__ W1, const float* __restrict__ b1,
        const float* __restrict__ W2, const float* __restrict__ b2,
        int outsel, float* __restrict__ dout, int out_is_ext, int do_relu) {
    __shared__ float INP[64 * 128];   // reused as MID after GEMM1
    __shared__ float Wsh[32 * 128];

    const float* feat = pick_feat(insel, x);
    float* out = out_is_ext ? dout : pick_out(outsel);

    int tid = threadIdx.x;
    int tx = tid & 31;   // col group: cols [tx*4, tx*4+4)
    int ty = tid >> 5;   // row group: rows [ty*8, ty*8+8)
    int base = blockIdx.x * 64;

    // load INP = feat + agg
    for (int i = tid; i < 64 * 32; i += 256) {
        int row = i >> 5, c4 = i & 31;
        int node = base + row;
        float4 v;
        if (node < N_NODES) {
            float4 a = ((const float4*)feat)[node * 32 + c4];
            float4 b = ((const float4*)g_agg)[node * 32 + c4];
            v = make_float4(a.x + b.x, a.y + b.y, a.z + b.z, a.w + b.w);
        } else {
            v = make_float4(0.f, 0.f, 0.f, 0.f);
        }
        ((float4*)INP)[i] = v;
    }

    const float4* INP4 = (const float4*)INP;
    const float4* W4   = (const float4*)Wsh;

    float4 acc[8];
#pragma unroll
    for (int r = 0; r < 8; r++) acc[r] = make_float4(0.f, 0.f, 0.f, 0.f);

    // GEMM 1: 4 k-chunks of 32
    for (int kc = 0; kc < 4; kc++) {
        __syncthreads();  // prev chunk FMAs done with Wsh (also covers INP load on kc=0)
        for (int i = tid; i < 32 * 32; i += 256)
            ((float4*)Wsh)[i] = ((const float4*)W1)[kc * 32 * 32 + i];
        __syncthreads();
        for (int k2 = 0; k2 < 32; k2 += 4) {
            float4 w0 = W4[(k2 + 0) * 32 + tx];
            float4 w1 = W4[(k2 + 1) * 32 + tx];
            float4 w2 = W4[(k2 + 2) * 32 + tx];
            float4 w3 = W4[(k2 + 3) * 32 + tx];
            int kidx = kc * 8 + (k2 >> 2);
#pragma unroll
            for (int r = 0; r < 8; r++) {
                float4 a = INP4[(ty * 8 + r) * 32 + kidx];
                acc[r].x += a.x * w0.x + a.y * w1.x + a.z * w2.x + a.w * w3.x;
                acc[r].y += a.x * w0.y + a.y * w1.y + a.z * w2.y + a.w * w3.y;
                acc[r].z += a.x * w0.z + a.y * w1.z + a.z * w2.z + a.w * w3.z;
                acc[r].w += a.x * w0.w + a.y * w1.w + a.z * w2.w + a.w * w3.w;
            }
        }
    }
    __syncthreads();  // all INP reads done -> safe to overwrite with MID

    // MID = relu(acc + b1), stored over INP
    {
        float4 bb = ((const float4*)b1)[tx];
#pragma unroll
        for (int r = 0; r < 8; r++) {
            float4 m;
            m.x = fmaxf(acc[r].x + bb.x, 0.f);
            m.y = fmaxf(acc[r].y + bb.y, 0.f);
            m.z = fmaxf(acc[r].z + bb.z, 0.f);
            m.w = fmaxf(acc[r].w + bb.w, 0.f);
            ((float4*)INP)[(ty * 8 + r) * 32 + tx] = m;
        }
    }

#pragma unroll
    for (int r = 0; r < 8; r++) acc[r] = make_float4(0.f, 0.f, 0.f, 0.f);

    // GEMM 2: 4 k-chunks of 32
    for (int kc = 0; kc < 4; kc++) {
        __syncthreads();  // MID writes visible / prev chunk done with Wsh
        for (int i = tid; i < 32 * 32; i += 256)
            ((float4*)Wsh)[i] = ((const float4*)W2)[kc * 32 * 32 + i];
        __syncthreads();
        for (int k2 = 0; k2 < 32; k2 += 4) {
            float4 w0 = W4[(k2 + 0) * 32 + tx];
            float4 w1 = W4[(k2 + 1) * 32 + tx];
            float4 w2 = W4[(k2 + 2) * 32 + tx];
            float4 w3 = W4[(k2 + 3) * 32 + tx];
            int kidx = kc * 8 + (k2 >> 2);
#pragma unroll
            for (int r = 0; r < 8; r++) {
                float4 a = INP4[(ty * 8 + r) * 32 + kidx];
                acc[r].x += a.x * w0.x + a.y * w1.x + a.z * w2.x + a.w * w3.x;
                acc[r].y += a.x * w0.y + a.y * w1.y + a.z * w2.y + a.w * w3.y;
                acc[r].z += a.x * w0.z + a.y * w1.z + a.z * w2.z + a.w * w3.z;
                acc[r].w += a.x * w0.w + a.y * w1.w + a.z * w2.w + a.w * w3.w;
            }
        }
    }

    // epilogue
    {
        float4 bb = ((const float4*)b2)[tx];
#pragma unroll
        for (int r = 0; r < 8; r++) {
            int node = base + ty * 8 + r;
            if (node < N_NODES) {
                float4 o;
                o.x = acc[r].x + bb.x;
                o.y = acc[r].y + bb.y;
                o.z = acc[r].z + bb.z;
                o.w = acc[r].w + bb.w;
                if (do_relu) {
                    o.x = fmaxf(o.x, 0.f); o.y = fmaxf(o.y, 0.f);
                    o.z = fmaxf(o.z, 0.f); o.w = fmaxf(o.w, 0.f);
                }
                ((float4*)out)[node * 32 + tx] = o;
            }
        }
    }
}

// ---------------- mean pool per graph (batch is sorted, int32) ----------------
__device__ __forceinline__ int lb_batch(const int* b, int v) {
    int lo = 0, hi = N_NODES;
    while (lo < hi) {
        int m = (lo + hi) >> 1;
        if (b[m] < v) lo = m + 1; else hi = m;
    }
    return lo;
}

__global__ void pool_k(const int* __restrict__ batch) {
    int g = blockIdx.x;      // 256 blocks
    int t = threadIdx.x;     // 128 threads, one per hidden dim
    int lo = lb_batch(batch, g);
    int hi = lb_batch(batch, g + 1);
    float s = 0.f;
    for (int n = lo; n < hi; n++) s += g_f1[n * HIDDEN + t];
    int cnt = hi - lo;
    float c = (float)(cnt > 0 ? cnt : 1);
    g_pooled[g * HIDDEN + t] = s / c;
}

// ---------------- final classifier: (256,128) @ (128,10) + bl ----------------
__global__ void final_k(const float* __restrict__ Wl, const float* __restrict__ bl,
                        float* __restrict__ out) {
    int i = blockIdx.x * blockDim.x + threadIdx.x;
    if (i < N_GRAPHS * N_CLASSES) {
        int g = i / N_CLASSES, c = i % N_CLASSES;
        float s = bl[c];
        const float* p = &g_pooled[g * HIDDEN];
        for (int k = 0; k < HIDDEN; k++) s += p[k] * Wl[k * N_CLASSES + c];
        out[i] = s;
    }
}

// ---------------- launcher: ONLY kernel launches ----------------
extern "C" void kernel_launch(void* const* d_in, const int* in_sizes, int n_in,
                              void* d_out, int out_size) {
    const float* x     = (const float*)d_in[0];
    const int*   ei    = (const int*)d_in[1];    // int32 per harness contract
    const int*   batch = (const int*)d_in[2];    // int32 per harness contract
    const float* W1    = (const float*)d_in[3];
    const float* b1    = (const float*)d_in[4];
    const float* W2    = (const float*)d_in[5];
    const float* b2    = (const float*)d_in[6];
    const float* Wl    = (const float*)d_in[7];
    const float* bl    = (const float*)d_in[8];
    float* out = (float*)d_out;

    // CSR build (reused across all 3 layers)
    zero_deg_k<<<(N_NODES + 255) / 256, 256>>>();
    hist_k<<<(N_EDGES + 255) / 256, 256>>>(ei);
    scan_k<<<1, 1024>>>();
    fill_k<<<(N_EDGES + 255) / 256, 256>>>(ei);

    const int AGG_BLOCKS = (N_NODES * 32 + 255) / 256;   // warp per node
    const int MLP_BLOCKS = (N_NODES + 63) / 64;

    // layer 0: x -> g_f1 (relu)
    agg_k<<<AGG_BLOCKS, 256>>>(0, x);
    mlp_k<<<MLP_BLOCKS, 256>>>(0, x, W1, b1, W2, b2, 1, nullptr, 0, 1);
    // layer 1: g_f1 -> g_f2 (relu)
    agg_k<<<AGG_BLOCKS, 256>>>(1, x);
    mlp_k<<<MLP_BLOCKS, 256>>>(1, x, W1, b1, W2, b2, 2, nullptr, 0, 1);
    // layer 2: g_f2 -> g_f1 (no relu)
    agg_k<<<AGG_BLOCKS, 256>>>(2, x);
    mlp_k<<<MLP_BLOCKS, 256>>>(2, x, W1, b1, W2, b2, 1, nullptr, 0, 0);

    pool_k<<<N_GRAPHS, HIDDEN>>>(batch);
    final_k<<<(N_GRAPHS * N_CLASSES + 255) / 256, 256>>>(Wl, bl, out);
}

// round 4
// speedup vs baseline: 1.1785x; 1.1785x over previous
#include <cuda_runtime.h>
#include <cstdint>

#define N_NODES  50000
#define N_EDGES  800000
#define HIDDEN   128
#define N_GRAPHS 256
#define N_CLASSES 10

// -------- device scratch (no allocations allowed) --------
__device__ __align__(16) float g_agg[N_NODES * HIDDEN];
__device__ __align__(16) float g_f1[N_NODES * HIDDEN];
__device__ __align__(16) float g_f2[N_NODES * HIDDEN];
__device__ int   g_deg[N_NODES];
__device__ int   g_off[N_NODES + 1];
__device__ int   g_cur[N_NODES];
__device__ int   g_csr[N_EDGES];
__device__ __align__(16) float g_pooled[N_GRAPHS * HIDDEN];
// tf32 hi/lo split weights (built once per call)
__device__ __align__(16) float g_W1h[HIDDEN * HIDDEN];
__device__ __align__(16) float g_W1l[HIDDEN * HIDDEN];
__device__ __align__(16) float g_W2h[HIDDEN * HIDDEN];
__device__ __align__(16) float g_W2l[HIDDEN * HIDDEN];

__device__ __forceinline__ const float* pick_feat(int sel, const float* x) {
    return sel == 0 ? x : (sel == 1 ? g_f1 : g_f2);
}
__device__ __forceinline__ float* pick_out(int sel) {
    return sel == 1 ? g_f1 : g_f2;
}
__device__ __forceinline__ int clamp_node(int v) {
    v = v < 0 ? 0 : v;
    return v >= N_NODES ? N_NODES - 1 : v;
}
__device__ __forceinline__ float tf32_hi(float x) {
    uint32_t u; asm("cvt.rna.tf32.f32 %0, %1;" : "=r"(u) : "f"(x));
    return __uint_as_float(u);
}

// ---------------- CSR build ----------------
__global__ void zero_deg_k() {
    int i = blockIdx.x * blockDim.x + threadIdx.x;
    if (i < N_NODES) g_deg[i] = 0;
}

__global__ void hist_k(const int* __restrict__ ei) {
    int e = blockIdx.x * blockDim.x + threadIdx.x;
    if (e < N_EDGES) {
        int d = clamp_node(ei[N_EDGES + e]);
        atomicAdd(&g_deg[d], 1);
    }
}

__global__ void scan_k() {
    const int T = 1024;
    const int ITEMS = (N_NODES + T - 1) / T;
    int tid = threadIdx.x;
    int base = tid * ITEMS;
    int s = 0;
    for (int i = 0; i < ITEMS; i++) {
        int idx = base + i;
        s += (idx < N_NODES) ? g_deg[idx] : 0;
    }
    __shared__ int sh[T];
    sh[tid] = s;
    __syncthreads();
    for (int d = 1; d < T; d <<= 1) {
        int t = (tid >= d) ? sh[tid - d] : 0;
        __syncthreads();
        sh[tid] += t;
        __syncthreads();
    }
    int run = sh[tid] - s;
    for (int i = 0; i < ITEMS; i++) {
        int idx = base + i;
        if (idx < N_NODES) {
            g_off[idx] = run;
            g_cur[idx] = run;
            run += g_deg[idx];
        }
    }
    if (tid == T - 1) g_off[N_NODES] = sh[T - 1];
}

__global__ void fill_k(const int* __restrict__ ei) {
    int e = blockIdx.x * blockDim.x + threadIdx.x;
    if (e < N_EDGES) {
        int s = clamp_node(ei[e]);
        int d = clamp_node(ei[N_EDGES + e]);
        int slot = atomicAdd(&g_cur[d], 1);
        if (slot >= 0 && slot < N_EDGES) g_csr[slot] = s;
    }
}

// ---------------- weight split: W = Wh(tf32) + Wl ----------------
__global__ void split_w_k(const float* __restrict__ W1, const float* __restrict__ W2) {
    int i = blockIdx.x * blockDim.x + threadIdx.x;
    if (i < HIDDEN * HIDDEN) {
        float w = W1[i]; float h = tf32_hi(w);
        g_W1h[i] = h; g_W1l[i] = w - h;
        w = W2[i]; h = tf32_hi(w);
        g_W2h[i] = h; g_W2l[i] = w - h;
    }
}

// ---------------- edge aggregation: warp per node ----------------
__global__ void agg_k(int insel, const float* __restrict__ x) {
    int w    = (blockIdx.x * blockDim.x + threadIdx.x) >> 5;
    int lane = threadIdx.x & 31;
    if (w >= N_NODES) return;
    const float* feat = pick_feat(insel, x);
    int lo = g_off[w], hi = g_off[w + 1];
    const float4* f4 = (const float4*)feat;
    float4 acc = make_float4(0.f, 0.f, 0.f, 0.f);
    for (int j = lo; j < hi; j++) {
        int s = g_csr[j];
        float4 v = f4[s * 32 + lane];
        acc.x += v.x; acc.y += v.y; acc.z += v.z; acc.w += v.w;
    }
    ((float4*)g_agg)[w * 32 + lane] = acc;
}

// ---------------- tensor-core fused 2-layer MLP (3xTF32) ----------------
// block: 128 nodes x 128 cols, 256 threads (8 warps, warp tile 32x64)
// smem: INP 128x132 f32 (reused for MID/OUT) + WH/WL chunks 32x136
#define INP_S 132
#define W_S   136

#define MMA_TF32(C, A0, A1, A2, A3, B0, B1)                                 \
    asm volatile(                                                           \
        "mma.sync.aligned.m16n8k8.row.col.f32.tf32.tf32.f32 "               \
        "{%0,%1,%2,%3}, {%4,%5,%6,%7}, {%8,%9}, {%0,%1,%2,%3};"             \
        : "+f"(C[0]), "+f"(C[1]), "+f"(C[2]), "+f"(C[3])                    \
        : "r"(A0), "r"(A1), "r"(A2), "r"(A3), "r"(B0), "r"(B1))

__device__ __forceinline__ void mma_kstep(
        const float* __restrict__ INP, const float* __restrict__ WH,
        const float* __restrict__ WL, int wm, int wn, int lane,
        int kk, int kb, float acc[2][8][4]) {
    uint32_t ah[2][4], al[2][4];
#pragma unroll
    for (int mt = 0; mt < 2; mt++) {
        int r0 = wm + mt * 16 + (lane >> 2);
        int c0 = kk + (lane & 3);
        float a0 = INP[r0 * INP_S + c0];
        float a1 = INP[(r0 + 8) * INP_S + c0];
        float a2 = INP[r0 * INP_S + c0 + 4];
        float a3 = INP[(r0 + 8) * INP_S + c0 + 4];
        float h0 = tf32_hi(a0), h1 = tf32_hi(a1), h2 = tf32_hi(a2), h3 = tf32_hi(a3);
        ah[mt][0] = __float_as_uint(h0); al[mt][0] = __float_as_uint(a0 - h0);
        ah[mt][1] = __float_as_uint(h1); al[mt][1] = __float_as_uint(a1 - h1);
        ah[mt][2] = __float_as_uint(h2); al[mt][2] = __float_as_uint(a2 - h2);
        ah[mt][3] = __float_as_uint(h3); al[mt][3] = __float_as_uint(a3 - h3);
    }
#pragma unroll
    for (int nt = 0; nt < 8; nt++) {
        int bn = wn + nt * 8 + (lane >> 2);
        int br = kb + (lane & 3);
        uint32_t bh0 = __float_as_uint(WH[br * W_S + bn]);
        uint32_t bh1 = __float_as_uint(WH[(br + 4) * W_S + bn]);
        uint32_t bl0 = __float_as_uint(WL[br * W_S + bn]);
        uint32_t bl1 = __float_as_uint(WL[(br + 4) * W_S + bn]);
#pragma unroll
        for (int mt = 0; mt < 2; mt++) {
            MMA_TF32(acc[mt][nt], ah[mt][0], ah[mt][1], ah[mt][2], ah[mt][3], bh0, bh1);
            MMA_TF32(acc[mt][nt], al[mt][0], al[mt][1], al[mt][2], al[mt][3], bh0, bh1);
            MMA_TF32(acc[mt][nt], ah[mt][0], ah[mt][1], ah[mt][2], ah[mt][3], bl0, bl1);
        }
    }
}

__global__ void __launch_bounds__(256) mlp_tc_k(
        int insel, const float* __restrict__ x,
        const float* __restrict__ b1, const float* __restrict__ b2,
        int outsel, int do_relu) {
    extern __shared__ float sm[];
    float* INP = sm;                        // 128*132
    float* WH  = sm + 128 * INP_S;          // 32*136
    float* WL  = WH + 32 * W_S;             // 32*136

    const float* feat = pick_feat(insel, x);
    float* out = pick_out(outsel);

    int tid = threadIdx.x;
    int lane = tid & 31, warp = tid >> 5;
    int base = blockIdx.x * 128;
    const int wm = (warp >> 1) * 32;   // 0,32,64,96
    const int wn = (warp & 1) * 64;    // 0,64

    // load INP = feat + agg (zero-pad tail rows)
    for (int i = tid; i < 128 * 32; i += 256) {
        int row = i >> 5, c4 = i & 31;
        int node = base + row;
        float4 v = make_float4(0.f, 0.f, 0.f, 0.f);
        if (node < N_NODES) {
            float4 a = ((const float4*)feat)[node * 32 + c4];
            float4 g = ((const float4*)g_agg)[node * 32 + c4];
            v = make_float4(a.x + g.x, a.y + g.y, a.z + g.z, a.w + g.w);
        }
        *(float4*)&INP[row * INP_S + c4 * 4] = v;
    }

    float acc[2][8][4];
#pragma unroll
    for (int mt = 0; mt < 2; mt++)
#pragma unroll
        for (int nt = 0; nt < 8; nt++)
#pragma unroll
            for (int r = 0; r < 4; r++) acc[mt][nt][r] = 0.f;

    // ---- GEMM 1: (INP) @ W1 ----
    for (int kc = 0; kc < 4; kc++) {
        __syncthreads();
        for (int i = tid; i < 32 * 32; i += 256) {
            int r = i >> 5, c4 = i & 31;
            *(float4*)&WH[r * W_S + c4 * 4] = ((const float4*)g_W1h)[(kc * 32 + r) * 32 + c4];
            *(float4*)&WL[r * W_S + c4 * 4] = ((const float4*)g_W1l)[(kc * 32 + r) * 32 + c4];
        }
        __syncthreads();
#pragma unroll
        for (int ks = 0; ks < 4; ks++)
            mma_kstep(INP, WH, WL, wm, wn, lane, kc * 32 + ks * 8, ks * 8, acc);
    }
    __syncthreads();  // all INP reads done

    // MID = relu(acc + b1) -> overwrite INP
#pragma unroll
    for (int mt = 0; mt < 2; mt++) {
        int row = wm + mt * 16 + (lane >> 2);
#pragma unroll
        for (int nt = 0; nt < 8; nt++) {
            int col = wn + nt * 8 + 2 * (lane & 3);
            float2 bb = *(const float2*)(b1 + col);
            float2 v0, v1;
            v0.x = fmaxf(acc[mt][nt][0] + bb.x, 0.f);
            v0.y = fmaxf(acc[mt][nt][1] + bb.y, 0.f);
            v1.x = fmaxf(acc[mt][nt][2] + bb.x, 0.f);
            v1.y = fmaxf(acc[mt][nt][3] + bb.y, 0.f);
            *(float2*)&INP[row * INP_S + col] = v0;
            *(float2*)&INP[(row + 8) * INP_S + col] = v1;
        }
    }

#pragma unroll
    for (int mt = 0; mt < 2; mt++)
#pragma unroll
        for (int nt = 0; nt < 8; nt++)
#pragma unroll
            for (int r = 0; r < 4; r++) acc[mt][nt][r] = 0.f;

    // ---- GEMM 2: MID @ W2 ----
    for (int kc = 0; kc < 4; kc++) {
        __syncthreads();  // MID writes visible / prev chunk reads done
        for (int i = tid; i < 32 * 32; i += 256) {
            int r = i >> 5, c4 = i & 31;
            *(float4*)&WH[r * W_S + c4 * 4] = ((const float4*)g_W2h)[(kc * 32 + r) * 32 + c4];
            *(float4*)&WL[r * W_S + c4 * 4] = ((const float4*)g_W2l)[(kc * 32 + r) * 32 + c4];
        }
        __syncthreads();
#pragma unroll
        for (int ks = 0; ks < 4; ks++)
            mma_kstep(INP, WH, WL, wm, wn, lane, kc * 32 + ks * 8, ks * 8, acc);
    }
    __syncthreads();  // all MID reads done

    // OUT = (acc + b2) [relu?] -> overwrite INP, then coalesced copy out
#pragma unroll
    for (int mt = 0; mt < 2; mt++) {
        int row = wm + mt * 16 + (lane >> 2);
#pragma unroll
        for (int nt = 0; nt < 8; nt++) {
            int col = wn + nt * 8 + 2 * (lane & 3);
            float2 bb = *(const float2*)(b2 + col);
            float2 v0, v1;
            v0.x = acc[mt][nt][0] + bb.x;
            v0.y = acc[mt][nt][1] + bb.y;
            v1.x = acc[mt][nt][2] + bb.x;
            v1.y = acc[mt][nt][3] + bb.y;
            if (do_relu) {
                v0.x = fmaxf(v0.x, 0.f); v0.y = fmaxf(v0.y, 0.f);
                v1.x = fmaxf(v1.x, 0.f); v1.y = fmaxf(v1.y, 0.f);
            }
            *(float2*)&INP[row * INP_S + col] = v0;
            *(float2*)&INP[(row + 8) * INP_S + col] = v1;
        }
    }
    __syncthreads();

    for (int i = tid; i < 128 * 32; i += 256) {
        int row = i >> 5, c4 = i & 31;
        int node = base + row;
        if (node < N_NODES)
            ((float4*)out)[node * 32 + c4] = *(float4*)&INP[row * INP_S + c4 * 4];
    }
}

// ---------------- mean pool per graph (batch is sorted, int32) ----------------
__device__ __forceinline__ int lb_batch(const int* b, int v) {
    int lo = 0, hi = N_NODES;
    while (lo < hi) {
        int m = (lo + hi) >> 1;
        if (b[m] < v) lo = m + 1; else hi = m;
    }
    return lo;
}

__global__ void pool_k(const int* __restrict__ batch) {
    int g = blockIdx.x;
    int t = threadIdx.x;
    int lo = lb_batch(batch, g);
    int hi = lb_batch(batch, g + 1);
    float s = 0.f;
    for (int n = lo; n < hi; n++) s += g_f1[n * HIDDEN + t];
    int cnt = hi - lo;
    float c = (float)(cnt > 0 ? cnt : 1);
    g_pooled[g * HIDDEN + t] = s / c;
}

// ---------------- final classifier ----------------
__global__ void final_k(const float* __restrict__ Wl, const float* __restrict__ bl,
                        float* __restrict__ out) {
    int i = blockIdx.x * blockDim.x + threadIdx.x;
    if (i < N_GRAPHS * N_CLASSES) {
        int g = i / N_CLASSES, c = i % N_CLASSES;
        float s = bl[c];
        const float* p = &g_pooled[g * HIDDEN];
        for (int k = 0; k < HIDDEN; k++) s += p[k] * Wl[k * N_CLASSES + c];
        out[i] = s;
    }
}

// ---------------- launcher ----------------
extern "C" void kernel_launch(void* const* d_in, const int* in_sizes, int n_in,
                              void* d_out, int out_size) {
    const float* x     = (const float*)d_in[0];
    const int*   ei    = (const int*)d_in[1];
    const int*   batch = (const int*)d_in[2];
    const float* W1    = (const float*)d_in[3];
    const float* b1    = (const float*)d_in[4];
    const float* W2    = (const float*)d_in[5];
    const float* b2    = (const float*)d_in[6];
    const float* Wl    = (const float*)d_in[7];
    const float* bl    = (const float*)d_in[8];
    float* out = (float*)d_out;

    const int MLP_SMEM = (128 * INP_S + 2 * 32 * W_S) * sizeof(float);  // 102400 B
    cudaFuncSetAttribute(mlp_tc_k, cudaFuncAttributeMaxDynamicSharedMemorySize, MLP_SMEM);

    // CSR build + weight split (reused across all 3 layers)
    zero_deg_k<<<(N_NODES + 255) / 256, 256>>>();
    hist_k<<<(N_EDGES + 255) / 256, 256>>>(ei);
    split_w_k<<<(HIDDEN * HIDDEN + 255) / 256, 256>>>(W1, W2);
    scan_k<<<1, 1024>>>();
    fill_k<<<(N_EDGES + 255) / 256, 256>>>(ei);

    const int AGG_BLOCKS = (N_NODES * 32 + 255) / 256;
    const int MLP_BLOCKS = (N_NODES + 127) / 128;

    // layer 0: x -> g_f1 (relu)
    agg_k<<<AGG_BLOCKS, 256>>>(0, x);
    mlp_tc_k<<<MLP_BLOCKS, 256, MLP_SMEM>>>(0, x, b1, b2, 1, 1);
    // layer 1: g_f1 -> g_f2 (relu)
    agg_k<<<AGG_BLOCKS, 256>>>(1, x);
    mlp_tc_k<<<MLP_BLOCKS, 256, MLP_SMEM>>>(1, x, b1, b2, 2, 1);
    // layer 2: g_f2 -> g_f1 (no relu)
    agg_k<<<AGG_BLOCKS, 256>>>(2, x);
    mlp_tc_k<<<MLP_BLOCKS, 256, MLP_SMEM>>>(2, x, b1, b2, 1, 0);

    pool_k<<<N_GRAPHS, HIDDEN>>>(batch);
    final_k<<<(N_GRAPHS * N_CLASSES + 255) / 256, 256>>>(Wl, bl, out);
}

// round 5
// speedup vs baseline: 1.4401x; 1.2220x over previous
#include <cuda_runtime.h>
#include <cstdint>

#define N_NODES  50000
#define N_EDGES  800000
#define HIDDEN   128
#define N_GRAPHS 256
#define N_CLASSES 10

#define SCAN_BLK  512
#define SCAN_NBLK ((N_NODES + SCAN_BLK - 1) / SCAN_BLK)   // 98

// -------- device scratch (no allocations allowed) --------
__device__ __align__(16) float g_agg[N_NODES * HIDDEN];
__device__ __align__(16) float g_f1[N_NODES * HIDDEN];
__device__ __align__(16) float g_f2[N_NODES * HIDDEN];
__device__ int   g_deg[N_NODES];
__device__ int   g_off[N_NODES + 1];
__device__ int   g_cur[N_NODES];
__device__ int   g_csr[N_EDGES];
__device__ int   g_bsum[SCAN_NBLK];
__device__ int   g_boff[SCAN_NBLK];
__device__ __align__(16) float g_pooled[N_GRAPHS * HIDDEN];
// tf32 hi/lo split weights (built once per call)
__device__ __align__(16) float g_W1h[HIDDEN * HIDDEN];
__device__ __align__(16) float g_W1l[HIDDEN * HIDDEN];
__device__ __align__(16) float g_W2h[HIDDEN * HIDDEN];
__device__ __align__(16) float g_W2l[HIDDEN * HIDDEN];

__device__ __forceinline__ const float* pick_feat(int sel, const float* x) {
    return sel == 0 ? x : (sel == 1 ? g_f1 : g_f2);
}
__device__ __forceinline__ float* pick_out(int sel) {
    return sel == 1 ? g_f1 : g_f2;
}
__device__ __forceinline__ int clamp_node(int v) {
    v = v < 0 ? 0 : v;
    return v >= N_NODES ? N_NODES - 1 : v;
}
__device__ __forceinline__ float tf32_hi(float x) {
    uint32_t u; asm("cvt.rna.tf32.f32 %0, %1;" : "=r"(u) : "f"(x));
    return __uint_as_float(u);
}

// ---------------- CSR build ----------------
__global__ void zero_deg_k() {
    int i = blockIdx.x * blockDim.x + threadIdx.x;
    if (i < N_NODES) g_deg[i] = 0;
}

__global__ void hist_k(const int* __restrict__ ei) {
    int e = blockIdx.x * blockDim.x + threadIdx.x;
    if (e < N_EDGES) {
        int d = clamp_node(ei[N_EDGES + e]);
        atomicAdd(&g_deg[d], 1);
    }
}

// ---- 3-phase parallel scan of g_deg -> g_off (exclusive), g_cur copy ----
__global__ void scan1_k() {   // block partial sums
    __shared__ int sh[SCAN_BLK];
    int i = blockIdx.x * SCAN_BLK + threadIdx.x;
    int v = (i < N_NODES) ? g_deg[i] : 0;
    sh[threadIdx.x] = v;
    __syncthreads();
    for (int d = SCAN_BLK / 2; d > 0; d >>= 1) {
        if (threadIdx.x < d) sh[threadIdx.x] += sh[threadIdx.x + d];
        __syncthreads();
    }
    if (threadIdx.x == 0) g_bsum[blockIdx.x] = sh[0];
}

__global__ void scan2_k() {   // exclusive scan of 98 block sums (1 block, 128 thr)
    __shared__ int sh[128];
    int tid = threadIdx.x;
    int v = (tid < SCAN_NBLK) ? g_bsum[tid] : 0;
    sh[tid] = v;
    __syncthreads();
    for (int d = 1; d < 128; d <<= 1) {
        int t = (tid >= d) ? sh[tid - d] : 0;
        __syncthreads();
        sh[tid] += t;
        __syncthreads();
    }
    if (tid < SCAN_NBLK) g_boff[tid] = sh[tid] - v;   // exclusive
    if (tid == 127) g_off[N_NODES] = sh[127];         // total
}

__global__ void scan3_k() {   // block-local exclusive scan + offset
    __shared__ int sh[SCAN_BLK];
    int i = blockIdx.x * SCAN_BLK + threadIdx.x;
    int v = (i < N_NODES) ? g_deg[i] : 0;
    int tid = threadIdx.x;
    sh[tid] = v;
    __syncthreads();
    for (int d = 1; d < SCAN_BLK; d <<= 1) {
        int t = (tid >= d) ? sh[tid - d] : 0;
        __syncthreads();
        sh[tid] += t;
        __syncthreads();
    }
    if (i < N_NODES) {
        int off = g_boff[blockIdx.x] + sh[tid] - v;   // exclusive prefix
        g_off[i] = off;
        g_cur[i] = off;
    }
}

__global__ void fill_k(const int* __restrict__ ei) {
    int e = blockIdx.x * blockDim.x + threadIdx.x;
    if (e < N_EDGES) {
        int s = clamp_node(ei[e]);
        int d = clamp_node(ei[N_EDGES + e]);
        int slot = atomicAdd(&g_cur[d], 1);
        if (slot >= 0 && slot < N_EDGES) g_csr[slot] = s;
    }
}

// ---------------- weight split: W = Wh(tf32) + Wl ----------------
__global__ void split_w_k(const float* __restrict__ W1, const float* __restrict__ W2) {
    int i = blockIdx.x * blockDim.x + threadIdx.x;
    if (i < HIDDEN * HIDDEN) {
        float w = W1[i]; float h = tf32_hi(w);
        g_W1h[i] = h; g_W1l[i] = w - h;
        w = W2[i]; h = tf32_hi(w);
        g_W2h[i] = h; g_W2l[i] = w - h;
    }
}

// ---------------- edge aggregation: warp per node ----------------
// g_agg[node] = feat[node] + sum_{s in csr[node]} feat[s]   (GIN eps=0 input)
__global__ void agg_k(int insel, const float* __restrict__ x) {
    int w    = (blockIdx.x * blockDim.x + threadIdx.x) >> 5;
    int lane = threadIdx.x & 31;
    if (w >= N_NODES) return;
    const float* feat = pick_feat(insel, x);
    int lo = g_off[w], hi = g_off[w + 1];
    const float4* f4 = (const float4*)feat;
    float4 acc = f4[w * 32 + lane];   // self feature
    for (int j = lo; j < hi; j++) {
        int s = g_csr[j];
        float4 v = f4[s * 32 + lane];
        acc.x += v.x; acc.y += v.y; acc.z += v.z; acc.w += v.w;
    }
    ((float4*)g_agg)[w * 32 + lane] = acc;
}

// ---------------- tensor-core fused 2-layer MLP (3xTF32) ----------------
// block: 128 nodes x 128 cols, 256 threads (8 warps, warp tile 32x64)
// smem: INP 128x132 f32 (reused for MID/OUT) + WH/WL chunks 32x136
#define INP_S 132
#define W_S   136

#define MMA_TF32(C, A0, A1, A2, A3, B0, B1)                                 \
    asm volatile(                                                           \
        "mma.sync.aligned.m16n8k8.row.col.f32.tf32.tf32.f32 "               \
        "{%0,%1,%2,%3}, {%4,%5,%6,%7}, {%8,%9}, {%0,%1,%2,%3};"             \
        : "+f"(C[0]), "+f"(C[1]), "+f"(C[2]), "+f"(C[3])                    \
        : "r"(A0), "r"(A1), "r"(A2), "r"(A3), "r"(B0), "r"(B1))

__device__ __forceinline__ void mma_kstep(
        const float* __restrict__ INP, const float* __restrict__ WH,
        const float* __restrict__ WL, int wm, int wn, int lane,
        int kk, int kb, float acc[2][8][4]) {
    uint32_t ah[2][4], al[2][4];
#pragma unroll
    for (int mt = 0; mt < 2; mt++) {
        int r0 = wm + mt * 16 + (lane >> 2);
        int c0 = kk + (lane & 3);
        float a0 = INP[r0 * INP_S + c0];
        float a1 = INP[(r0 + 8) * INP_S + c0];
        float a2 = INP[r0 * INP_S + c0 + 4];
        float a3 = INP[(r0 + 8) * INP_S + c0 + 4];
        float h0 = tf32_hi(a0), h1 = tf32_hi(a1), h2 = tf32_hi(a2), h3 = tf32_hi(a3);
        ah[mt][0] = __float_as_uint(h0); al[mt][0] = __float_as_uint(a0 - h0);
        ah[mt][1] = __float_as_uint(h1); al[mt][1] = __float_as_uint(a1 - h1);
        ah[mt][2] = __float_as_uint(h2); al[mt][2] = __float_as_uint(a2 - h2);
        ah[mt][3] = __float_as_uint(h3); al[mt][3] = __float_as_uint(a3 - h3);
    }
#pragma unroll
    for (int nt = 0; nt < 8; nt++) {
        int bn = wn + nt * 8 + (lane >> 2);
        int br = kb + (lane & 3);
        uint32_t bh0 = __float_as_uint(WH[br * W_S + bn]);
        uint32_t bh1 = __float_as_uint(WH[(br + 4) * W_S + bn]);
        uint32_t bl0 = __float_as_uint(WL[br * W_S + bn]);
        uint32_t bl1 = __float_as_uint(WL[(br + 4) * W_S + bn]);
#pragma unroll
        for (int mt = 0; mt < 2; mt++) {
            MMA_TF32(acc[mt][nt], ah[mt][0], ah[mt][1], ah[mt][2], ah[mt][3], bh0, bh1);
            MMA_TF32(acc[mt][nt], al[mt][0], al[mt][1], al[mt][2], al[mt][3], bh0, bh1);
            MMA_TF32(acc[mt][nt], ah[mt][0], ah[mt][1], ah[mt][2], ah[mt][3], bl0, bl1);
        }
    }
}

__global__ void __launch_bounds__(256) mlp_tc_k(
        const float* __restrict__ b1, const float* __restrict__ b2,
        int outsel, int do_relu) {
    extern __shared__ float sm[];
    float* INP = sm;                        // 128*132
    float* WH  = sm + 128 * INP_S;          // 32*136
    float* WL  = WH + 32 * W_S;             // 32*136

    float* out = pick_out(outsel);

    int tid = threadIdx.x;
    int lane = tid & 31, warp = tid >> 5;
    int base = blockIdx.x * 128;
    const int wm = (warp >> 1) * 32;   // 0,32,64,96
    const int wn = (warp & 1) * 64;    // 0,64

    // load INP = g_agg (already feat+sum), zero-pad tail rows
    for (int i = tid; i < 128 * 32; i += 256) {
        int row = i >> 5, c4 = i & 31;
        int node = base + row;
        float4 v = make_float4(0.f, 0.f, 0.f, 0.f);
        if (node < N_NODES)
            v = ((const float4*)g_agg)[node * 32 + c4];
        *(float4*)&INP[row * INP_S + c4 * 4] = v;
    }

    float acc[2][8][4];
#pragma unroll
    for (int mt = 0; mt < 2; mt++)
#pragma unroll
        for (int nt = 0; nt < 8; nt++)
#pragma unroll
            for (int r = 0; r < 4; r++) acc[mt][nt][r] = 0.f;

    // ---- GEMM 1: INP @ W1 ----
    for (int kc = 0; kc < 4; kc++) {
        __syncthreads();
        for (int i = tid; i < 32 * 32; i += 256) {
            int r = i >> 5, c4 = i & 31;
            *(float4*)&WH[r * W_S + c4 * 4] = ((const float4*)g_W1h)[(kc * 32 + r) * 32 + c4];
            *(float4*)&WL[r * W_S + c4 * 4] = ((const float4*)g_W1l)[(kc * 32 + r) * 32 + c4];
        }
        __syncthreads();
#pragma unroll
        for (int ks = 0; ks < 4; ks++)
            mma_kstep(INP, WH, WL, wm, wn, lane, kc * 32 + ks * 8, ks * 8, acc);
    }
    __syncthreads();  // all INP reads done

    // MID = relu(acc + b1) -> overwrite INP
#pragma unroll
    for (int mt = 0; mt < 2; mt++) {
        int row = wm + mt * 16 + (lane >> 2);
#pragma unroll
        for (int nt = 0; nt < 8; nt++) {
            int col = wn + nt * 8 + 2 * (lane & 3);
            float2 bb = *(const float2*)(b1 + col);
            float2 v0, v1;
            v0.x = fmaxf(acc[mt][nt][0] + bb.x, 0.f);
            v0.y = fmaxf(acc[mt][nt][1] + bb.y, 0.f);
            v1.x = fmaxf(acc[mt][nt][2] + bb.x, 0.f);
            v1.y = fmaxf(acc[mt][nt][3] + bb.y, 0.f);
            *(float2*)&INP[row * INP_S + col] = v0;
            *(float2*)&INP[(row + 8) * INP_S + col] = v1;
        }
    }

#pragma unroll
    for (int mt = 0; mt < 2; mt++)
#pragma unroll
        for (int nt = 0; nt < 8; nt++)
#pragma unroll
            for (int r = 0; r < 4; r++) acc[mt][nt][r] = 0.f;

    // ---- GEMM 2: MID @ W2 ----
    for (int kc = 0; kc < 4; kc++) {
        __syncthreads();
        for (int i = tid; i < 32 * 32; i += 256) {
            int r = i >> 5, c4 = i & 31;
            *(float4*)&WH[r * W_S + c4 * 4] = ((const float4*)g_W2h)[(kc * 32 + r) * 32 + c4];
            *(float4*)&WL[r * W_S + c4 * 4] = ((const float4*)g_W2l)[(kc * 32 + r) * 32 + c4];
        }
        __syncthreads();
#pragma unroll
        for (int ks = 0; ks < 4; ks++)
            mma_kstep(INP, WH, WL, wm, wn, lane, kc * 32 + ks * 8, ks * 8, acc);
    }
    __syncthreads();  // all MID reads done

    // OUT = (acc + b2) [relu?] -> overwrite INP, then coalesced copy out
#pragma unroll
    for (int mt = 0; mt < 2; mt++) {
        int row = wm + mt * 16 + (lane >> 2);
#pragma unroll
        for (int nt = 0; nt < 8; nt++) {
            int col = wn + nt * 8 + 2 * (lane & 3);
            float2 bb = *(const float2*)(b2 + col);
            float2 v0, v1;
            v0.x = acc[mt][nt][0] + bb.x;
            v0.y = acc[mt][nt][1] + bb.y;
            v1.x = acc[mt][nt][2] + bb.x;
            v1.y = acc[mt][nt][3] + bb.y;
            if (do_relu) {
                v0.x = fmaxf(v0.x, 0.f); v0.y = fmaxf(v0.y, 0.f);
                v1.x = fmaxf(v1.x, 0.f); v1.y = fmaxf(v1.y, 0.f);
            }
            *(float2*)&INP[row * INP_S + col] = v0;
            *(float2*)&INP[(row + 8) * INP_S + col] = v1;
        }
    }
    __syncthreads();

    for (int i = tid; i < 128 * 32; i += 256) {
        int row = i >> 5, c4 = i & 31;
        int node = base + row;
        if (node < N_NODES)
            ((float4*)out)[node * 32 + c4] = *(float4*)&INP[row * INP_S + c4 * 4];
    }
}

// ---------------- mean pool per graph (batch is sorted, int32) ----------------
__device__ __forceinline__ int lb_batch(const int* b, int v) {
    int lo = 0, hi = N_NODES;
    while (lo < hi) {
        int m = (lo + hi) >> 1;
        if (b[m] < v) lo = m + 1; else hi = m;
    }
    return lo;
}

__global__ void pool_k(const int* __restrict__ batch) {
    int g = blockIdx.x;
    int t = threadIdx.x;
    int lo = lb_batch(batch, g);
    int hi = lb_batch(batch, g + 1);
    float s = 0.f;
    for (int n = lo; n < hi; n++) s += g_f1[n * HIDDEN + t];
    int cnt = hi - lo;
    float c = (float)(cnt > 0 ? cnt : 1);
    g_pooled[g * HIDDEN + t] = s / c;
}

// ---------------- final classifier ----------------
__global__ void final_k(const float* __restrict__ Wl, const float* __restrict__ bl,
                        float* __restrict__ out) {
    int i = blockIdx.x * blockDim.x + threadIdx.x;
    if (i < N_GRAPHS * N_CLASSES) {
        int g = i / N_CLASSES, c = i % N_CLASSES;
        float s = bl[c];
        const float* p = &g_pooled[g * HIDDEN];
        for (int k = 0; k < HIDDEN; k++) s += p[k] * Wl[k * N_CLASSES + c];
        out[i] = s;
    }
}

// ---------------- launcher ----------------
extern "C" void kernel_launch(void* const* d_in, const int* in_sizes, int n_in,
                              void* d_out, int out_size) {
    const float* x     = (const float*)d_in[0];
    const int*   ei    = (const int*)d_in[1];
    const int*   batch = (const int*)d_in[2];
    const float* W1    = (const float*)d_in[3];
    const float* b1    = (const float*)d_in[4];
    const float* W2    = (const float*)d_in[5];
    const float* b2    = (const float*)d_in[6];
    const float* Wl    = (const float*)d_in[7];
    const float* bl    = (const float*)d_in[8];
    float* out = (float*)d_out;

    const int MLP_SMEM = (128 * INP_S + 2 * 32 * W_S) * sizeof(float);  // 102400 B
    cudaFuncSetAttribute(mlp_tc_k, cudaFuncAttributeMaxDynamicSharedMemorySize, MLP_SMEM);

    // CSR build + weight split (reused across all 3 layers)
    zero_deg_k<<<(N_NODES + 255) / 256, 256>>>();
    hist_k<<<(N_EDGES + 255) / 256, 256>>>(ei);
    split_w_k<<<(HIDDEN * HIDDEN + 255) / 256, 256>>>(W1, W2);
    scan1_k<<<SCAN_NBLK, SCAN_BLK>>>();
    scan2_k<<<1, 128>>>();
    scan3_k<<<SCAN_NBLK, SCAN_BLK>>>();
    fill_k<<<(N_EDGES + 255) / 256, 256>>>(ei);

    const int AGG_BLOCKS = (N_NODES * 32 + 255) / 256;
    const int MLP_BLOCKS = (N_NODES + 127) / 128;

    // layer 0: x -> g_f1 (relu)
    agg_k<<<AGG_BLOCKS, 256>>>(0, x);
    mlp_tc_k<<<MLP_BLOCKS, 256, MLP_SMEM>>>(b1, b2, 1, 1);
    // layer 1: g_f1 -> g_f2 (relu)
    agg_k<<<AGG_BLOCKS, 256>>>(1, x);
    mlp_tc_k<<<MLP_BLOCKS, 256, MLP_SMEM>>>(b1, b2, 2, 1);
    // layer 2: g_f2 -> g_f1 (no relu)
    agg_k<<<AGG_BLOCKS, 256>>>(2, x);
    mlp_tc_k<<<MLP_BLOCKS, 256, MLP_SMEM>>>(b1, b2, 1, 0);

    pool_k<<<N_GRAPHS, HIDDEN>>>(batch);
    final_k<<<(N_GRAPHS * N_CLASSES + 255) / 256, 256>>>(Wl, bl, out);
}

// round 6
// speedup vs baseline: 1.8979x; 1.3179x over previous
#include <cuda_runtime.h>
#include <cuda_bf16.h>
#include <cstdint>

#define N_NODES  50000
#define N_EDGES  800000
#define HIDDEN   128
#define N_GRAPHS 256
#define N_CLASSES 10

#define SCAN_BLK  512
#define SCAN_NBLK ((N_NODES + SCAN_BLK - 1) / SCAN_BLK)   // 98

// -------- device scratch (no allocations allowed) --------
__device__ __align__(16) float g_agg[N_NODES * HIDDEN];
__device__ __align__(16) float g_f1[N_NODES * HIDDEN];
__device__ __align__(16) float g_f2[N_NODES * HIDDEN];
__device__ int   g_deg[N_NODES];
__device__ int   g_off[N_NODES + 1];
__device__ int   g_cur[N_NODES];
__device__ int   g_csr[N_EDGES];
__device__ int   g_bsum[SCAN_NBLK];
__device__ int   g_boff[SCAN_NBLK];
__device__ __align__(16) float g_pooled[N_GRAPHS * HIDDEN];
// bf16 hi/lo split weights, TRANSPOSED to [n][k] (built once per call)
__device__ __align__(16) __nv_bfloat16 g_W1hT[HIDDEN * HIDDEN];
__device__ __align__(16) __nv_bfloat16 g_W1lT[HIDDEN * HIDDEN];
__device__ __align__(16) __nv_bfloat16 g_W2hT[HIDDEN * HIDDEN];
__device__ __align__(16) __nv_bfloat16 g_W2lT[HIDDEN * HIDDEN];

__device__ __forceinline__ const float* pick_feat(int sel, const float* x) {
    return sel == 0 ? x : (sel == 1 ? g_f1 : g_f2);
}
__device__ __forceinline__ float* pick_out(int sel) {
    return sel == 1 ? g_f1 : g_f2;
}
__device__ __forceinline__ int clamp_node(int v) {
    v = v < 0 ? 0 : v;
    return v >= N_NODES ? N_NODES - 1 : v;
}

// ---------------- CSR build ----------------
__global__ void zero_deg_k() {
    int i = blockIdx.x * blockDim.x + threadIdx.x;
    if (i < N_NODES) g_deg[i] = 0;
}

__global__ void hist_k(const int* __restrict__ ei) {
    int e = blockIdx.x * blockDim.x + threadIdx.x;
    if (e < N_EDGES) {
        int d = clamp_node(ei[N_EDGES + e]);
        atomicAdd(&g_deg[d], 1);
    }
}

__global__ void scan1_k() {   // block partial sums
    __shared__ int sh[SCAN_BLK];
    int i = blockIdx.x * SCAN_BLK + threadIdx.x;
    int v = (i < N_NODES) ? g_deg[i] : 0;
    sh[threadIdx.x] = v;
    __syncthreads();
    for (int d = SCAN_BLK / 2; d > 0; d >>= 1) {
        if (threadIdx.x < d) sh[threadIdx.x] += sh[threadIdx.x + d];
        __syncthreads();
    }
    if (threadIdx.x == 0) g_bsum[blockIdx.x] = sh[0];
}

__global__ void scan2_k() {   // exclusive scan of 98 block sums
    __shared__ int sh[128];
    int tid = threadIdx.x;
    int v = (tid < SCAN_NBLK) ? g_bsum[tid] : 0;
    sh[tid] = v;
    __syncthreads();
    for (int d = 1; d < 128; d <<= 1) {
        int t = (tid >= d) ? sh[tid - d] : 0;
        __syncthreads();
        sh[tid] += t;
        __syncthreads();
    }
    if (tid < SCAN_NBLK) g_boff[tid] = sh[tid] - v;
    if (tid == 127) g_off[N_NODES] = sh[127];
}

__global__ void scan3_k() {   // block-local exclusive scan + offset
    __shared__ int sh[SCAN_BLK];
    int i = blockIdx.x * SCAN_BLK + threadIdx.x;
    int v = (i < N_NODES) ? g_deg[i] : 0;
    int tid = threadIdx.x;
    sh[tid] = v;
    __syncthreads();
    for (int d = 1; d < SCAN_BLK; d <<= 1) {
        int t = (tid >= d) ? sh[tid - d] : 0;
        __syncthreads();
        sh[tid] += t;
        __syncthreads();
    }
    if (i < N_NODES) {
        int off = g_boff[blockIdx.x] + sh[tid] - v;
        g_off[i] = off;
        g_cur[i] = off;
    }
}

__global__ void fill_k(const int* __restrict__ ei) {
    int e = blockIdx.x * blockDim.x + threadIdx.x;
    if (e < N_EDGES) {
        int s = clamp_node(ei[e]);
        int d = clamp_node(ei[N_EDGES + e]);
        int slot = atomicAdd(&g_cur[d], 1);
        if (slot >= 0 && slot < N_EDGES) g_csr[slot] = s;
    }
}

// ---------------- weight split+transpose: W[k][n] -> Wh/Wl [n][k] bf16 ----------------
__global__ void split_w_k(const float* __restrict__ W1, const float* __restrict__ W2) {
    int i = blockIdx.x * blockDim.x + threadIdx.x;   // i = n*128 + k
    if (i < HIDDEN * HIDDEN) {
        int n = i >> 7, k = i & 127;
        float w = W1[k * HIDDEN + n];
        __nv_bfloat16 h = __float2bfloat16_rn(w);
        g_W1hT[i] = h;
        g_W1lT[i] = __float2bfloat16_rn(w - __bfloat162float(h));
        w = W2[k * HIDDEN + n];
        h = __float2bfloat16_rn(w);
        g_W2hT[i] = h;
        g_W2lT[i] = __float2bfloat16_rn(w - __bfloat162float(h));
    }
}

// ---------------- edge aggregation: warp per node ----------------
// g_agg[node] = feat[node] + sum_{s in csr[node]} feat[s]
__global__ void agg_k(int insel, const float* __restrict__ x) {
    int w    = (blockIdx.x * blockDim.x + threadIdx.x) >> 5;
    int lane = threadIdx.x & 31;
    if (w >= N_NODES) return;
    const float* feat = pick_feat(insel, x);
    int lo = g_off[w], hi = g_off[w + 1];
    const float4* f4 = (const float4*)feat;
    float4 acc = f4[w * 32 + lane];   // self feature
    for (int j = lo; j < hi; j++) {
        int s = g_csr[j];
        float4 v = f4[s * 32 + lane];
        acc.x += v.x; acc.y += v.y; acc.z += v.z; acc.w += v.w;
    }
    ((float4*)g_agg)[w * 32 + lane] = acc;
}

// ---------------- tensor-core fused 2-layer MLP (3xBF16 split) ----------------
// block: 128 nodes x 128 cols, 256 threads (8 warps, warp tile 32x64)
// smem: INPh/INPl 128x136 bf16 each (split activations, reused for MID and f32 OUT)
//       WHT/WLT   128x72  bf16 each (transposed weight k-chunk of 64)
#define INP_S 136   // bf16 stride: conflict-free A frag loads
#define WT_S  72    // bf16 stride: conflict-free B frag loads
#define OUT_S 132   // f32 stride for epilogue staging

#define MMA_BF16(C, A0, A1, A2, A3, B0, B1)                                 \
    asm volatile(                                                           \
        "mma.sync.aligned.m16n8k16.row.col.f32.bf16.bf16.f32 "              \
        "{%0,%1,%2,%3}, {%4,%5,%6,%7}, {%8,%9}, {%0,%1,%2,%3};"             \
        : "+f"(C[0]), "+f"(C[1]), "+f"(C[2]), "+f"(C[3])                    \
        : "r"(A0), "r"(A1), "r"(A2), "r"(A3), "r"(B0), "r"(B1))

__device__ __forceinline__ uint32_t pack_bf16x2(float a, float b) {
    __nv_bfloat162 t = __floats2bfloat162_rn(a, b);
    return *(uint32_t*)&t;
}

// one k16 step for one warp
__device__ __forceinline__ void mma_kstep_bf16(
        const __nv_bfloat16* __restrict__ INPh, const __nv_bfloat16* __restrict__ INPl,
        const __nv_bfloat16* __restrict__ WHT,  const __nv_bfloat16* __restrict__ WLT,
        int wm, int wn, int lane, int kk /*global k of step*/, int kb /*k within chunk*/,
        float acc[2][8][4]) {
    uint32_t ah[2][4], al[2][4];
    int k0 = (lane & 3) * 2;
#pragma unroll
    for (int mt = 0; mt < 2; mt++) {
        int r = wm + mt * 16 + (lane >> 2);
        ah[mt][0] = *(const uint32_t*)&INPh[r * INP_S + kk + k0];
        ah[mt][1] = *(const uint32_t*)&INPh[(r + 8) * INP_S + kk + k0];
        ah[mt][2] = *(const uint32_t*)&INPh[r * INP_S + kk + k0 + 8];
        ah[mt][3] = *(const uint32_t*)&INPh[(r + 8) * INP_S + kk + k0 + 8];
        al[mt][0] = *(const uint32_t*)&INPl[r * INP_S + kk + k0];
        al[mt][1] = *(const uint32_t*)&INPl[(r + 8) * INP_S + kk + k0];
        al[mt][2] = *(const uint32_t*)&INPl[r * INP_S + kk + k0 + 8];
        al[mt][3] = *(const uint32_t*)&INPl[(r + 8) * INP_S + kk + k0 + 8];
    }
#pragma unroll
    for (int nt = 0; nt < 8; nt++) {
        int n = wn + nt * 8 + (lane >> 2);
        uint32_t bh0 = *(const uint32_t*)&WHT[n * WT_S + kb + k0];
        uint32_t bh1 = *(const uint32_t*)&WHT[n * WT_S + kb + k0 + 8];
        uint32_t bl0 = *(const uint32_t*)&WLT[n * WT_S + kb + k0];
        uint32_t bl1 = *(const uint32_t*)&WLT[n * WT_S + kb + k0 + 8];
#pragma unroll
        for (int mt = 0; mt < 2; mt++) {
            MMA_BF16(acc[mt][nt], ah[mt][0], ah[mt][1], ah[mt][2], ah[mt][3], bh0, bh1);
            MMA_BF16(acc[mt][nt], al[mt][0], al[mt][1], al[mt][2], al[mt][3], bh0, bh1);
            MMA_BF16(acc[mt][nt], ah[mt][0], ah[mt][1], ah[mt][2], ah[mt][3], bl0, bl1);
        }
    }
}

__global__ void __launch_bounds__(256, 2) mlp_tc_k(
        const float* __restrict__ b1, const float* __restrict__ b2,
        int outsel, int do_relu) {
    extern __shared__ char smraw[];
    __nv_bfloat16* INPh = (__nv_bfloat16*)smraw;                 // 128*136*2 = 34816
    __nv_bfloat16* INPl = INPh + 128 * INP_S;                    // 34816
    __nv_bfloat16* WHT  = INPl + 128 * INP_S;                    // 128*72*2 = 18432
    __nv_bfloat16* WLT  = WHT + 128 * WT_S;                      // 18432
    float* FOUT = (float*)smraw;  // aliases INPh+INPl (67584B <= 69632B)

    float* out = pick_out(outsel);

    int tid = threadIdx.x;
    int lane = tid & 31, warp = tid >> 5;
    int base = blockIdx.x * 128;
    const int wm = (warp >> 1) * 32;   // 0,32,64,96
    const int wn = (warp & 1) * 64;    // 0,64

    // load INP = g_agg, split into bf16 hi/lo (zero-pad tail rows)
    for (int i = tid; i < 128 * 32; i += 256) {
        int row = i >> 5, c4 = i & 31;
        int node = base + row;
        float4 v = make_float4(0.f, 0.f, 0.f, 0.f);
        if (node < N_NODES)
            v = ((const float4*)g_agg)[node * 32 + c4];
        uint32_t h01 = pack_bf16x2(v.x, v.y);
        uint32_t h23 = pack_bf16x2(v.z, v.w);
        float hx = __bfloat162float(__float2bfloat16_rn(v.x));
        float hy = __bfloat162float(__float2bfloat16_rn(v.y));
        float hz = __bfloat162float(__float2bfloat16_rn(v.z));
        float hw = __bfloat162float(__float2bfloat16_rn(v.w));
        uint32_t l01 = pack_bf16x2(v.x - hx, v.y - hy);
        uint32_t l23 = pack_bf16x2(v.z - hz, v.w - hw);
        uint2* dh = (uint2*)&INPh[row * INP_S + c4 * 4];
        uint2* dl = (uint2*)&INPl[row * INP_S + c4 * 4];
        *dh = make_uint2(h01, h23);
        *dl = make_uint2(l01, l23);
    }

    float acc[2][8][4];
#pragma unroll
    for (int mt = 0; mt < 2; mt++)
#pragma unroll
        for (int nt = 0; nt < 8; nt++)
#pragma unroll
            for (int r = 0; r < 4; r++) acc[mt][nt][r] = 0.f;

    // ---- GEMM 1: INP @ W1 (2 k-chunks of 64) ----
    for (int kc = 0; kc < 2; kc++) {
        __syncthreads();
        for (int i = tid; i < 128 * 8; i += 256) {   // 8 uint4 per n-row (64 bf16)
            int n = i >> 3, q = i & 7;
            *(uint4*)&WHT[n * WT_S + q * 8] =
                *(const uint4*)&g_W1hT[n * HIDDEN + kc * 64 + q * 8];
            *(uint4*)&WLT[n * WT_S + q * 8] =
                *(const uint4*)&g_W1lT[n * HIDDEN + kc * 64 + q * 8];
        }
        __syncthreads();
#pragma unroll
        for (int ks = 0; ks < 4; ks++)
            mma_kstep_bf16(INPh, INPl, WHT, WLT, wm, wn, lane,
                           kc * 64 + ks * 16, ks * 16, acc);
    }
    __syncthreads();  // all INP reads done

    // MID = relu(acc + b1) -> split bf16, overwrite INPh/INPl
#pragma unroll
    for (int mt = 0; mt < 2; mt++) {
        int row = wm + mt * 16 + (lane >> 2);
#pragma unroll
        for (int nt = 0; nt < 8; nt++) {
            int col = wn + nt * 8 + 2 * (lane & 3);
            float2 bb = *(const float2*)(b1 + col);
            float m0 = fmaxf(acc[mt][nt][0] + bb.x, 0.f);
            float m1 = fmaxf(acc[mt][nt][1] + bb.y, 0.f);
            float m2 = fmaxf(acc[mt][nt][2] + bb.x, 0.f);
            float m3 = fmaxf(acc[mt][nt][3] + bb.y, 0.f);
            float h0 = __bfloat162float(__float2bfloat16_rn(m0));
            float h1 = __bfloat162float(__float2bfloat16_rn(m1));
            float h2 = __bfloat162float(__float2bfloat16_rn(m2));
            float h3 = __bfloat162float(__float2bfloat16_rn(m3));
            *(uint32_t*)&INPh[row * INP_S + col]       = pack_bf16x2(m0, m1);
            *(uint32_t*)&INPl[row * INP_S + col]       = pack_bf16x2(m0 - h0, m1 - h1);
            *(uint32_t*)&INPh[(row + 8) * INP_S + col] = pack_bf16x2(m2, m3);
            *(uint32_t*)&INPl[(row + 8) * INP_S + col] = pack_bf16x2(m2 - h2, m3 - h3);
        }
    }

#pragma unroll
    for (int mt = 0; mt < 2; mt++)
#pragma unroll
        for (int nt = 0; nt < 8; nt++)
#pragma unroll
            for (int r = 0; r < 4; r++) acc[mt][nt][r] = 0.f;

    // ---- GEMM 2: MID @ W2 ----
    for (int kc = 0; kc < 2; kc++) {
        __syncthreads();  // MID writes visible / prev chunk reads done
        for (int i = tid; i < 128 * 8; i += 256) {
            int n = i >> 3, q = i & 7;
            *(uint4*)&WHT[n * WT_S + q * 8] =
                *(const uint4*)&g_W2hT[n * HIDDEN + kc * 64 + q * 8];
            *(uint4*)&WLT[n * WT_S + q * 8] =
                *(const uint4*)&g_W2lT[n * HIDDEN + kc * 64 + q * 8];
        }
        __syncthreads();
#pragma unroll
        for (int ks = 0; ks < 4; ks++)
            mma_kstep_bf16(INPh, INPl, WHT, WLT, wm, wn, lane,
                           kc * 64 + ks * 16, ks * 16, acc);
    }
    __syncthreads();  // all MID reads done -> FOUT may alias INP

    // OUT = (acc + b2) [relu?] -> f32 staging, then coalesced copy out
#pragma unroll
    for (int mt = 0; mt < 2; mt++) {
        int row = wm + mt * 16 + (lane >> 2);
#pragma unroll
        for (int nt = 0; nt < 8; nt++) {
            int col = wn + nt * 8 + 2 * (lane & 3);
            float2 bb = *(const float2*)(b2 + col);
            float2 v0, v1;
            v0.x = acc[mt][nt][0] + bb.x;
            v0.y = acc[mt][nt][1] + bb.y;
            v1.x = acc[mt][nt][2] + bb.x;
            v1.y = acc[mt][nt][3] + bb.y;
            if (do_relu) {
                v0.x = fmaxf(v0.x, 0.f); v0.y = fmaxf(v0.y, 0.f);
                v1.x = fmaxf(v1.x, 0.f); v1.y = fmaxf(v1.y, 0.f);
            }
            *(float2*)&FOUT[row * OUT_S + col] = v0;
            *(float2*)&FOUT[(row + 8) * OUT_S + col] = v1;
        }
    }
    __syncthreads();

    for (int i = tid; i < 128 * 32; i += 256) {
        int row = i >> 5, c4 = i & 31;
        int node = base + row;
        if (node < N_NODES)
            ((float4*)out)[node * 32 + c4] = *(float4*)&FOUT[row * OUT_S + c4 * 4];
    }
}

// ---------------- mean pool per graph (batch is sorted, int32) ----------------
__device__ __forceinline__ int lb_batch(const int* b, int v) {
    int lo = 0, hi = N_NODES;
    while (lo < hi) {
        int m = (lo + hi) >> 1;
        if (b[m] < v) lo = m + 1; else hi = m;
    }
    return lo;
}

__global__ void pool_k(const int* __restrict__ batch) {
    int g = blockIdx.x;
    int t = threadIdx.x;
    int lo = lb_batch(batch, g);
    int hi = lb_batch(batch, g + 1);
    float s = 0.f;
    for (int n = lo; n < hi; n++) s += g_f1[n * HIDDEN + t];
    int cnt = hi - lo;
    float c = (float)(cnt > 0 ? cnt : 1);
    g_pooled[g * HIDDEN + t] = s / c;
}

// ---------------- final classifier ----------------
__global__ void final_k(const float* __restrict__ Wl, const float* __restrict__ bl,
                        float* __restrict__ out) {
    int i = blockIdx.x * blockDim.x + threadIdx.x;
    if (i < N_GRAPHS * N_CLASSES) {
        int g = i / N_CLASSES, c = i % N_CLASSES;
        float s = bl[c];
        const float* p = &g_pooled[g * HIDDEN];
        for (int k = 0; k < HIDDEN; k++) s += p[k] * Wl[k * N_CLASSES + c];
        out[i] = s;
    }
}

// ---------------- launcher ----------------
extern "C" void kernel_launch(void* const* d_in, const int* in_sizes, int n_in,
                              void* d_out, int out_size) {
    const float* x     = (const float*)d_in[0];
    const int*   ei    = (const int*)d_in[1];
    const int*   batch = (const int*)d_in[2];
    const float* W1    = (const float*)d_in[3];
    const float* b1    = (const float*)d_in[4];
    const float* W2    = (const float*)d_in[5];
    const float* b2    = (const float*)d_in[6];
    const float* Wl    = (const float*)d_in[7];
    const float* bl    = (const float*)d_in[8];
    float* out = (float*)d_out;

    const int MLP_SMEM = (2 * 128 * INP_S + 2 * 128 * WT_S) * 2;  // 106496 B
    cudaFuncSetAttribute(mlp_tc_k, cudaFuncAttributeMaxDynamicSharedMemorySize, MLP_SMEM);

    // CSR build + weight split (reused across all 3 layers)
    zero_deg_k<<<(N_NODES + 255) / 256, 256>>>();
    hist_k<<<(N_EDGES + 255) / 256, 256>>>(ei);
    split_w_k<<<(HIDDEN * HIDDEN + 255) / 256, 256>>>(W1, W2);
    scan1_k<<<SCAN_NBLK, SCAN_BLK>>>();
    scan2_k<<<1, 128>>>();
    scan3_k<<<SCAN_NBLK, SCAN_BLK>>>();
    fill_k<<<(N_EDGES + 255) / 256, 256>>>(ei);

    const int AGG_BLOCKS = (N_NODES * 32 + 255) / 256;
    const int MLP_BLOCKS = (N_NODES + 127) / 128;

    // layer 0: x -> g_f1 (relu)
    agg_k<<<AGG_BLOCKS, 256>>>(0, x);
    mlp_tc_k<<<MLP_BLOCKS, 256, MLP_SMEM>>>(b1, b2, 1, 1);
    // layer 1: g_f1 -> g_f2 (relu)
    agg_k<<<AGG_BLOCKS, 256>>>(1, x);
    mlp_tc_k<<<MLP_BLOCKS, 256, MLP_SMEM>>>(b1, b2, 2, 1);
    // layer 2: g_f2 -> g_f1 (no relu)
    agg_k<<<AGG_BLOCKS, 256>>>(2, x);
    mlp_tc_k<<<MLP_BLOCKS, 256, MLP_SMEM>>>(b1, b2, 1, 0);

    pool_k<<<N_GRAPHS, HIDDEN>>>(batch);
    final_k<<<(N_GRAPHS * N_CLASSES + 255) / 256, 256>>>(Wl, bl, out);
}